// round 14
// baseline (speedup 1.0000x reference)
#include <cuda_runtime.h>
#include <math.h>

#define N_ROIS 32768
#define M_GT   4096
#define D_FEAT 512
#define GX 32
#define GY 32
#define NCELL (GX*GY)               // 1024
#define CELL_INV (1.0f/32.0f)
#define CAP 32                      // bin capacity (lambda~4, overflow ~1e-16)
#define LPR 8                       // lanes per roi in kmatch
#define NBLK (N_ROIS/32)            // 1024 kmatch blocks, 32 rois each
#define NBINBLK 16                  // blocks that bin gt (16*256 = 4096)

// ---------------- device scratch (no allocations allowed) ----------------
__device__ float4 g_binA[NCELL * CAP];   // (x2, y2, -x1, -y1)
__device__ int    g_binI[NCELL * CAP];   // original gt index (tie-break only)
__device__ int    g_cnt[NCELL];          // zeroed by kfinal for next replay
__device__ int    g_binDone;             // producer/consumer flag (reset by kfinal)
__device__ int    g_nmatch;
__device__ int    g_flag[NBLK];          // block has >=1 masked roi
__device__ float  g_partial[NBLK * D_FEAT];

__device__ __forceinline__ int clampi(int v, int lo, int hi) {
    return v < lo ? lo : (v > hi ? hi : v);
}

// === fused: [blocks 0-15: gt binning] -> spin -> match -> feat partial ===
__global__ void __launch_bounds__(256) kmatch(const float* __restrict__ gt,
                                              const float* __restrict__ rois,
                                              const float* __restrict__ pred,
                                              const float* __restrict__ feat,
                                              float* __restrict__ out) {
    __shared__ float s_mask[32];
    __shared__ int   s_rows[32];
    __shared__ int   s_total;
    int t   = threadIdx.x;
    int blk = blockIdx.x;

    // ---- phase 1: blocks 0..15 bin the gt boxes (wave-1 guaranteed) ----
    if (blk < NBINBLK) {
        int g = blk * 256 + t;               // 0..4095, exact
        if (g == 0) g_nmatch = 0;
        float4 b = __ldg(&reinterpret_cast<const float4*>(gt)[g]);
        float cx = 0.5f * (b.x + b.z), cy = 0.5f * (b.y + b.w);
        int ix = clampi((int)floorf(cx * CELL_INV), 0, GX - 1);
        int iy = clampi((int)floorf(cy * CELL_INV), 0, GY - 1);
        int c = iy * GX + ix;
        int slot = atomicAdd(&g_cnt[c], 1);
        if (slot < CAP) {                    // guard: drop, never corrupt
            g_binA[c * CAP + slot] = make_float4(b.z, b.w, -b.x, -b.y);
            g_binI[c * CAP + slot] = g;
        }
        __syncthreads();
        if (t == 0) { __threadfence(); atomicAdd(&g_binDone, 1); }
    }

    // ---- spin until all bins published (producers never wait) ----
    if (t == 0) {
        volatile int* p = &g_binDone;
        while (*p < NBINBLK) __nanosleep(64);
    }
    __syncthreads();
    __threadfence();                         // acquire for bin reads

    // ---- phase 2: matching, 8 lanes per roi, candidate-split (R8) ----
    int par = t & (LPR - 1);
    int i = blk * 32 + (t >> 3);             // roi index

    float4 r = __ldg(&reinterpret_cast<const float4*>(rois)[i]);
    float rx1 = r.x, ry1 = r.y, rx2 = r.z, ry2 = r.w;
    float nrx1 = -rx1, nry1 = -ry1;
    float areaA = (rx2 - rx1) * (ry2 - ry1);

    // EXACT window: IoU>0.5 requires the gt center strictly inside the roi.
    int cx0 = clampi((int)floorf(rx1 * CELL_INV), 0, GX - 1);
    int cx1 = clampi((int)floorf(rx2 * CELL_INV), 0, GX - 1);
    int cy0 = clampi((int)floorf(ry1 * CELL_INV), 0, GY - 1);
    int cy1 = clampi((int)floorf(ry2 * CELL_INV), 0, GY - 1);

    // iou_a > iou_b <=> inter_a*S_b > inter_b*S_a  (S = areaA + areaB)
    float bi = 0.0f, bS = 1.0f;
    int bidx = 0x7fffffff, bk = -1;

    for (int cy = cy0; cy <= cy1; ++cy) {
        int cbase = cy * GX;
        for (int cx = cx0; cx <= cx1; ++cx) {
            int c = cbase + cx;
            int cnt = __ldg(&g_cnt[c]);
            if (cnt > CAP) cnt = CAP;
            int b2 = c * CAP;
            for (int s = par; s < cnt; s += LPR) {
                float4 A = __ldg(&g_binA[b2 + s]);
                float w = fminf(rx2, A.x) + fminf(nrx1, A.z);
                float h = fminf(ry2, A.y) + fminf(nry1, A.w);
                w = fmaxf(w, 0.0f);
                h = fmaxf(h, 0.0f);
                float inter = w * h;
                if (inter > 0.0f) {
                    float areaB = (A.x + A.z) * (A.y + A.w);
                    float S  = areaA + areaB;
                    float p1 = inter * bS;
                    float p2 = bi * S;
                    if (p1 > p2) {
                        bi = inter; bS = S; bk = b2 + s;
                        bidx = __ldg(&g_binI[b2 + s]);
                    } else if (p1 == p2) {       // rare exact tie: lazy idx
                        int idx = __ldg(&g_binI[b2 + s]);
                        if (idx < bidx) {
                            bi = inter; bS = S; bidx = idx; bk = b2 + s;
                        }
                    }
                }
            }
        }
    }

    // butterfly combine across the 8 lanes of this roi (deterministic)
    #pragma unroll
    for (int off = 1; off < LPR; off <<= 1) {
        float obi  = __shfl_xor_sync(0xffffffffu, bi, off);
        float obS  = __shfl_xor_sync(0xffffffffu, bS, off);
        int   oidx = __shfl_xor_sync(0xffffffffu, bidx, off);
        int   obk  = __shfl_xor_sync(0xffffffffu, bk, off);
        float p1 = obi * bS;
        float p2 = bi * obS;
        if (p1 > p2 || (p1 == p2 && oidx < bidx)) {
            bi = obi; bS = obS; bidx = oidx; bk = obk;
        }
    }

    float maxiou = bi / (bS - bi);
    float maskf  = (maxiou > 0.5f) ? 1.0f : 0.0f;

    if (par == 0) {                          // epilogue by lead lane
        s_mask[t >> 3] = maskf;

        // inverse_transform (with +1 on w/h, matching reference)
        float4 d = __ldg(&reinterpret_cast<const float4*>(pred)[i]);
        float w0 = rx2 - rx1 + 1.0f, h0 = ry2 - ry1 + 1.0f;
        float cxx = rx1 + 0.5f * w0, cyy = ry1 + 0.5f * h0;
        float pcx = d.x * w0 + cxx,  pcy = d.y * h0 + cyy;
        float pw = expf(d.z) * w0,   ph = expf(d.w) * h0;
        float f1 = pcx - 0.5f * pw, f2 = pcy - 0.5f * ph;
        float f3 = pcx + 0.5f * pw, f4 = pcy + 0.5f * ph;

        float loss = 0.0f;
        if (maskf > 0.0f) {
            float4 A = __ldg(&g_binA[bk]);
            float gx2 = A.x, gy2 = A.y, gx1 = -A.z, gy1 = -A.w;
            float iw = fmaxf(fminf(f3, gx2) - fmaxf(f1, gx1), 0.0f);
            float ih = fmaxf(fminf(f4, gy2) - fmaxf(f2, gy1), 0.0f);
            float it = iw * ih;
            float aa = (f3 - f1) * (f4 - f2);
            float ab = (gx2 - gx1) * (gy2 - gy1);
            float io = it / (aa + ab - it);
            loss = -logf(io + 0.1f);
        }

        out[i] = loss;
        float2* outr = reinterpret_cast<float2*>(out + N_ROIS + 2);
        outr[2 * i + 0] = make_float2(f1 * maskf, f2 * maskf);
        outr[2 * i + 1] = make_float2(f3 * maskf, f4 * maskf);
    }
    __syncthreads();

    // ---- phase 3: compact masked rows (warp 0) + feat partial ----
    if (t < 32) {
        float m = s_mask[t];
        unsigned bal = __ballot_sync(0xffffffffu, m > 0.0f);
        int tot = __popc(bal);
        if (m > 0.0f)
            s_rows[__popc(bal & ((1u << t) - 1u))] = t;
        if (t == 0) {
            s_total = tot;
            g_flag[blk] = (tot > 0) ? 1 : 0;
            if (tot) atomicAdd(&g_nmatch, tot);
        }
    }
    __syncthreads();

    int total = s_total;
    if (total > 0) {
        float a0 = 0.0f, a1 = 0.0f;
        const float* fb = feat + (size_t)blk * 32 * D_FEAT;
        int j = 0;
        for (; j + 2 <= total; j += 2) {     // unroll x2 for load MLP
            int q0 = s_rows[j], q1 = s_rows[j + 1];
            float v0 = fb[q0 * D_FEAT + t];
            float v1 = fb[q0 * D_FEAT + t + 256];
            float v2 = fb[q1 * D_FEAT + t];
            float v3 = fb[q1 * D_FEAT + t + 256];
            a0 += v0 + v2;
            a1 += v1 + v3;
        }
        if (j < total) {
            int q0 = s_rows[j];
            a0 += fb[q0 * D_FEAT + t];
            a1 += fb[q0 * D_FEAT + t + 256];
        }
        g_partial[blk * D_FEAT + t]       = a0;
        g_partial[blk * D_FEAT + t + 256] = a1;
    }
}

// ====== final: flag-gated partial sum + scalars + replay resets ======
__global__ void __launch_bounds__(D_FEAT) kfinal(float* __restrict__ out) {
    __shared__ float s[D_FEAT];
    int t = threadIdx.x;                     // 512 threads, one column each
    float c0 = 0.0f;
    #pragma unroll 8
    for (int b = 0; b < NBLK; ++b) {
        if (g_flag[b])                       // warp-uniform branch
            c0 += g_partial[b * D_FEAT + t];
    }
    s[t] = fabsf(c0);
    __syncthreads();
    #pragma unroll
    for (int off = D_FEAT / 2; off > 0; off >>= 1) {
        if (t < off) s[t] += s[t + off];
        __syncthreads();
    }
    if (t == 0) {
        out[N_ROIS]         = (float)g_nmatch;   // n_matched
        out[N_ROIS + 1]     = (float)N_ROIS;     // num_rois
        out[5 * N_ROIS + 2] = s[0];              // feat_loss
        g_binDone = 0;                           // reset for next replay
    }
    // reset bin counters for the next graph replay
    g_cnt[t]       = 0;
    g_cnt[t + 512] = 0;
}

// ---------------- launch ----------------
extern "C" void kernel_launch(void* const* d_in, const int* in_sizes, int n_in,
                              void* d_out, int out_size) {
    const float* rois = (const float*)d_in[0];
    const float* pred = (const float*)d_in[1];
    const float* gt   = (const float*)d_in[2];
    const float* feat = (const float*)d_in[3];
    float* out = (float*)d_out;

    kmatch<<<NBLK, 256>>>(gt, rois, pred, feat, out);
    kfinal<<<1, D_FEAT>>>(out);
}

// round 16
// speedup vs baseline: 2.7211x; 2.7211x over previous
#include <cuda_runtime.h>
#include <math.h>

#define N_ROIS 32768
#define M_GT   4096
#define D_FEAT 512
#define GX 32
#define GY 32
#define NCELL (GX*GY)               // 1024
#define CELL_INV (1.0f/32.0f)
#define CAP 32                      // bin capacity (lambda~4, overflow ~1e-16)
#define NFEAT_BLK 128               // kfeat blocks, 256 interleaved rows each
#define LPR 8                       // lanes per roi in kmatch

// ---------------- device scratch (no allocations allowed) ----------------
__device__ float4 g_binA[NCELL * CAP];   // (x2, y2, -x1, -y1)
__device__ int    g_binI[NCELL * CAP];   // original gt index (tie-break only)
__device__ int    g_cnt[NCELL];          // zero at start of every replay
__device__ int    g_nmatch;
__device__ int    g_done;
__device__ float  g_maskf[N_ROIS];
__device__ float  g_partial[NFEAT_BLK * D_FEAT];

__device__ __forceinline__ int clampi(int v, int lo, int hi) {
    return v < lo ? lo : (v > hi ? hi : v);
}

// ====== bin: one fully-parallel pass, direct fixed-capacity bins ======
__global__ void __launch_bounds__(256) kbin(const float* __restrict__ gt) {
    int i = blockIdx.x * 256 + threadIdx.x;
    if (i == 0) { g_nmatch = 0; g_done = 0; }   // for THIS replay (pre-kmatch)
    if (i >= M_GT) return;
    float4 b = __ldg(&reinterpret_cast<const float4*>(gt)[i]);
    float cx = 0.5f * (b.x + b.z), cy = 0.5f * (b.y + b.w);
    int ix = clampi((int)floorf(cx * CELL_INV), 0, GX - 1);
    int iy = clampi((int)floorf(cy * CELL_INV), 0, GY - 1);
    int c = iy * GX + ix;
    int slot = atomicAdd(&g_cnt[c], 1);
    if (slot < CAP) {                            // guard: drop, never corrupt
        g_binA[c * CAP + slot] = make_float4(b.z, b.w, -b.x, -b.y);
        g_binI[c * CAP + slot] = i;
    }
}

// ============ match: 8 lanes per roi, butterfly combine (R8) ============
__global__ void __launch_bounds__(256) kmatch(const float* __restrict__ rois,
                                              const float* __restrict__ pred,
                                              float* __restrict__ out) {
    __shared__ int s_wcnt[8];
    int t = threadIdx.x;
    int lane = t & 31, warp = t >> 5;
    int par = t & (LPR - 1);                 // candidate-stride lane
    int i = blockIdx.x * (256 / LPR) + (t / LPR);  // roi index

    float4 r = __ldg(&reinterpret_cast<const float4*>(rois)[i]);
    float rx1 = r.x, ry1 = r.y, rx2 = r.z, ry2 = r.w;
    float nrx1 = -rx1, nry1 = -ry1;
    float areaA = (rx2 - rx1) * (ry2 - ry1);

    // EXACT window: IoU>0.5 requires the gt center strictly inside the roi.
    int cx0 = clampi((int)floorf(rx1 * CELL_INV), 0, GX - 1);
    int cx1 = clampi((int)floorf(rx2 * CELL_INV), 0, GX - 1);
    int cy0 = clampi((int)floorf(ry1 * CELL_INV), 0, GY - 1);
    int cy1 = clampi((int)floorf(ry2 * CELL_INV), 0, GY - 1);

    // iou_a > iou_b <=> inter_a*S_b > inter_b*S_a  (S = areaA + areaB)
    float bi = 0.0f, bS = 1.0f;
    int bidx = 0x7fffffff, bk = -1;

    for (int cy = cy0; cy <= cy1; ++cy) {
        int cbase = cy * GX;
        for (int cx = cx0; cx <= cx1; ++cx) {
            int c = cbase + cx;
            int cnt = __ldg(&g_cnt[c]);
            if (cnt > CAP) cnt = CAP;
            int b2 = c * CAP;
            for (int s = par; s < cnt; s += LPR) {
                float4 A = __ldg(&g_binA[b2 + s]);
                float w = fminf(rx2, A.x) + fminf(nrx1, A.z);
                float h = fminf(ry2, A.y) + fminf(nry1, A.w);
                w = fmaxf(w, 0.0f);
                h = fmaxf(h, 0.0f);
                float inter = w * h;
                if (inter > 0.0f) {
                    float areaB = (A.x + A.z) * (A.y + A.w);
                    float S  = areaA + areaB;
                    float p1 = inter * bS;
                    float p2 = bi * S;
                    if (p1 > p2) {
                        bi = inter; bS = S; bk = b2 + s;
                        bidx = __ldg(&g_binI[b2 + s]);
                    } else if (p1 == p2) {       // rare exact tie: lazy idx
                        int idx = __ldg(&g_binI[b2 + s]);
                        if (idx < bidx) {
                            bi = inter; bS = S; bidx = idx; bk = b2 + s;
                        }
                    }
                }
            }
        }
    }

    // butterfly combine across the LPR lanes of this roi (deterministic)
    #pragma unroll
    for (int off = 1; off < LPR; off <<= 1) {
        float obi  = __shfl_xor_sync(0xffffffffu, bi, off);
        float obS  = __shfl_xor_sync(0xffffffffu, bS, off);
        int   oidx = __shfl_xor_sync(0xffffffffu, bidx, off);
        int   obk  = __shfl_xor_sync(0xffffffffu, bk, off);
        float p1 = obi * bS;
        float p2 = bi * obS;
        if (p1 > p2 || (p1 == p2 && oidx < bidx)) {
            bi = obi; bS = obS; bidx = oidx; bk = obk;
        }
    }

    float maxiou = bi / (bS - bi);
    float maskf  = (maxiou > 0.5f) ? 1.0f : 0.0f;

    // n_matched: count par==0 lanes only
    unsigned bal = __ballot_sync(0xffffffffu, (par == 0) && maskf > 0.0f);
    if (lane == 0) s_wcnt[warp] = __popc(bal);
    __syncthreads();
    if (t == 0) {
        int tot = 0;
        #pragma unroll
        for (int w = 0; w < 8; ++w) tot += s_wcnt[w];
        if (tot) atomicAdd(&g_nmatch, tot);
    }

    if (par != 0) return;                  // epilogue by lead lane only

    // inverse_transform (with +1 on w/h, matching reference)
    float4 d = __ldg(&reinterpret_cast<const float4*>(pred)[i]);
    float w0 = rx2 - rx1 + 1.0f, h0 = ry2 - ry1 + 1.0f;
    float cxx = rx1 + 0.5f * w0, cyy = ry1 + 0.5f * h0;
    float pcx = d.x * w0 + cxx,  pcy = d.y * h0 + cyy;
    float pw = expf(d.z) * w0,   ph = expf(d.w) * h0;
    float f1 = pcx - 0.5f * pw, f2 = pcy - 0.5f * ph;
    float f3 = pcx + 0.5f * pw, f4 = pcy + 0.5f * ph;

    float loss = 0.0f;
    if (maskf > 0.0f) {
        float4 A = __ldg(&g_binA[bk]);
        float gx2 = A.x, gy2 = A.y, gx1 = -A.z, gy1 = -A.w;
        float iw = fmaxf(fminf(f3, gx2) - fmaxf(f1, gx1), 0.0f);
        float ih = fmaxf(fminf(f4, gy2) - fmaxf(f2, gy1), 0.0f);
        float it = iw * ih;
        float aa = (f3 - f1) * (f4 - f2);
        float ab = (gx2 - gx1) * (gy2 - gy1);
        float io = it / (aa + ab - it);
        loss = -logf(io + 0.1f);
    }

    out[i] = loss;
    float2* outr = reinterpret_cast<float2*>(out + N_ROIS + 2);
    outr[2 * i + 0] = make_float2(f1 * maskf, f2 * maskf);
    outr[2 * i + 1] = make_float2(f3 * maskf, f4 * maskf);
    g_maskf[i] = maskf;
}

// == feat: INTERLEAVED rows (balance masked rows across all 128 blocks) ==
// block b owns rows { b + 128*j : j = 0..255 }; masked rows concentrate in
// rois 0..4095, so striding spreads them ~32 per block instead of 256 on
// blocks 0-15 only.
__global__ void __launch_bounds__(256) kfeat(const float* __restrict__ feat,
                                             float* __restrict__ out) {
    __shared__ int   s_rows[256];
    __shared__ int   s_wcnt[8];
    __shared__ int   s_isLast;
    __shared__ float s_red[256];
    int t = threadIdx.x;
    int lane = t & 31, warp = t >> 5;
    int blk = blockIdx.x;

    float m = g_maskf[blk + NFEAT_BLK * t];      // strided row j = t
    unsigned bal = __ballot_sync(0xffffffffu, m != 0.0f);
    if (lane == 0) s_wcnt[warp] = __popc(bal);
    __syncthreads();
    int base = 0, total = 0;
    #pragma unroll
    for (int w = 0; w < 8; ++w) {
        int cw = s_wcnt[w];
        if (w < warp) base += cw;
        total += cw;
    }
    if (m != 0.0f)
        s_rows[base + __popc(bal & ((1u << lane) - 1u))] = t;  // store j
    __syncthreads();

    float a0 = 0.0f, a1 = 0.0f;
    int j = 0;
    for (; j + 4 <= total; j += 4) {          // unroll x4 for load MLP
        size_t r0 = (size_t)(blk + NFEAT_BLK * s_rows[j])     * D_FEAT;
        size_t r1 = (size_t)(blk + NFEAT_BLK * s_rows[j + 1]) * D_FEAT;
        size_t r2 = (size_t)(blk + NFEAT_BLK * s_rows[j + 2]) * D_FEAT;
        size_t r3 = (size_t)(blk + NFEAT_BLK * s_rows[j + 3]) * D_FEAT;
        float v0 = feat[r0 + t];
        float v1 = feat[r0 + t + 256];
        float v2 = feat[r1 + t];
        float v3 = feat[r1 + t + 256];
        float v4 = feat[r2 + t];
        float v5 = feat[r2 + t + 256];
        float v6 = feat[r3 + t];
        float v7 = feat[r3 + t + 256];
        a0 += (v0 + v2) + (v4 + v6);
        a1 += (v1 + v3) + (v5 + v7);
    }
    for (; j < total; ++j) {
        size_t r0 = (size_t)(blk + NFEAT_BLK * s_rows[j]) * D_FEAT;
        a0 += feat[r0 + t];
        a1 += feat[r0 + t + 256];
    }
    g_partial[blk * D_FEAT + t]       = a0;
    g_partial[blk * D_FEAT + t + 256] = a1;

    __threadfence();
    if (t == 0) s_isLast = (atomicAdd(&g_done, 1) == NFEAT_BLK - 1);
    __syncthreads();
    if (!s_isLast) return;

    float c0 = 0.0f, c1 = 0.0f;
    #pragma unroll 8
    for (int b = 0; b < NFEAT_BLK; ++b) {
        c0 += g_partial[b * D_FEAT + t];
        c1 += g_partial[b * D_FEAT + t + 256];
    }
    s_red[t] = fabsf(c0) + fabsf(c1);
    __syncthreads();
    #pragma unroll
    for (int off = 128; off > 0; off >>= 1) {
        if (t < off) s_red[t] += s_red[t + off];
        __syncthreads();
    }
    if (t == 0) {
        out[N_ROIS]         = (float)g_nmatch;   // n_matched
        out[N_ROIS + 1]     = (float)N_ROIS;     // num_rois
        out[5 * N_ROIS + 2] = s_red[0];          // feat_loss
    }
    // reset bin counters for the NEXT graph replay (consumed by then)
    #pragma unroll
    for (int j2 = 0; j2 < NCELL / 256; ++j2)
        g_cnt[t + j2 * 256] = 0;
}

// ---------------- launch ----------------
extern "C" void kernel_launch(void* const* d_in, const int* in_sizes, int n_in,
                              void* d_out, int out_size) {
    const float* rois = (const float*)d_in[0];
    const float* pred = (const float*)d_in[1];
    const float* gt   = (const float*)d_in[2];
    const float* feat = (const float*)d_in[3];
    float* out = (float*)d_out;

    kbin<<<(M_GT + 255) / 256, 256>>>(gt);
    kmatch<<<N_ROIS / (256 / LPR), 256>>>(rois, pred, out);
    kfeat<<<NFEAT_BLK, 256>>>(feat, out);
}

// round 17
// speedup vs baseline: 2.8672x; 1.0537x over previous
#include <cuda_runtime.h>
#include <math.h>

#define N_ROIS 32768
#define M_GT   4096
#define D_FEAT 512
#define GX 32
#define GY 32
#define NCELL (GX*GY)               // 1024
#define CELL_INV (1.0f/32.0f)
#define CAP 32                      // bin capacity (lambda~4, overflow ~1e-16)
#define NFEAT_BLK 128               // kfeat blocks, 256 interleaved rows each
#define LPR 8                       // lanes per roi in kmatch

// ---------------- device scratch (no allocations allowed) ----------------
__device__ float4 g_binA[NCELL * CAP];   // (x2, y2, -x1, -y1)
__device__ int    g_binI[NCELL * CAP];   // original gt index (tie-break only)
__device__ int    g_cnt[NCELL];          // zero at start of every replay
__device__ int    g_nmatch;
__device__ int    g_done;
__device__ float  g_maskf[N_ROIS];
__device__ float  g_partial[NFEAT_BLK * D_FEAT];

__device__ __forceinline__ int clampi(int v, int lo, int hi) {
    return v < lo ? lo : (v > hi ? hi : v);
}

// ====== bin: one fully-parallel pass, direct fixed-capacity bins ======
__global__ void __launch_bounds__(256) kbin(const float* __restrict__ gt) {
    int i = blockIdx.x * 256 + threadIdx.x;
    if (i == 0) { g_nmatch = 0; g_done = 0; }   // for THIS replay (pre-kmatch)
    if (i >= M_GT) return;
    float4 b = __ldg(&reinterpret_cast<const float4*>(gt)[i]);
    float cx = 0.5f * (b.x + b.z), cy = 0.5f * (b.y + b.w);
    int ix = clampi((int)floorf(cx * CELL_INV), 0, GX - 1);
    int iy = clampi((int)floorf(cy * CELL_INV), 0, GY - 1);
    int c = iy * GX + ix;
    int slot = atomicAdd(&g_cnt[c], 1);
    if (slot < CAP) {                            // guard: drop, never corrupt
        g_binA[c * CAP + slot] = make_float4(b.z, b.w, -b.x, -b.y);
        g_binI[c * CAP + slot] = i;
    }
}

// ==== match: 8 lanes/roi, candidate-split, SMEM-staged cell counts ====
__global__ void __launch_bounds__(256) kmatch(const float* __restrict__ rois,
                                              const float* __restrict__ pred,
                                              float* __restrict__ out) {
    __shared__ int s_cnt[NCELL];             // 4 KB: whole count table
    __shared__ int s_wcnt[8];
    int t = threadIdx.x;
    int lane = t & 31, warp = t >> 5;
    int par = t & (LPR - 1);                 // candidate-stride lane
    int i = blockIdx.x * (256 / LPR) + (t / LPR);  // roi index

    // stage g_cnt into smem: LDS 29cyc replaces L2 234cyc on the serial chain
    #pragma unroll
    for (int j = 0; j < NCELL / 256; ++j)
        s_cnt[t + j * 256] = g_cnt[t + j * 256];

    float4 r = __ldg(&reinterpret_cast<const float4*>(rois)[i]);
    float4 d = __ldg(&reinterpret_cast<const float4*>(pred)[i]);  // hoisted
    __syncthreads();

    float rx1 = r.x, ry1 = r.y, rx2 = r.z, ry2 = r.w;
    float nrx1 = -rx1, nry1 = -ry1;
    float areaA = (rx2 - rx1) * (ry2 - ry1);

    // EXACT window: IoU>0.5 requires the gt center strictly inside the roi.
    int cx0 = clampi((int)floorf(rx1 * CELL_INV), 0, GX - 1);
    int cx1 = clampi((int)floorf(rx2 * CELL_INV), 0, GX - 1);
    int cy0 = clampi((int)floorf(ry1 * CELL_INV), 0, GY - 1);
    int cy1 = clampi((int)floorf(ry2 * CELL_INV), 0, GY - 1);

    // iou_a > iou_b <=> inter_a*S_b > inter_b*S_a  (S = areaA + areaB)
    float bi = 0.0f, bS = 1.0f;
    int bidx = 0x7fffffff, bk = -1;

    for (int cy = cy0; cy <= cy1; ++cy) {
        int cbase = cy * GX;
        for (int cx = cx0; cx <= cx1; ++cx) {
            int c = cbase + cx;
            int cnt = s_cnt[c];              // LDS, not L2
            if (cnt > CAP) cnt = CAP;
            int b2 = c * CAP;
            for (int s = par; s < cnt; s += LPR) {
                float4 A = __ldg(&g_binA[b2 + s]);
                float w = fminf(rx2, A.x) + fminf(nrx1, A.z);
                float h = fminf(ry2, A.y) + fminf(nry1, A.w);
                w = fmaxf(w, 0.0f);
                h = fmaxf(h, 0.0f);
                float inter = w * h;
                if (inter > 0.0f) {
                    float areaB = (A.x + A.z) * (A.y + A.w);
                    float S  = areaA + areaB;
                    float p1 = inter * bS;
                    float p2 = bi * S;
                    if (p1 > p2) {
                        bi = inter; bS = S; bk = b2 + s;
                        bidx = __ldg(&g_binI[b2 + s]);
                    } else if (p1 == p2) {       // rare exact tie: lazy idx
                        int idx = __ldg(&g_binI[b2 + s]);
                        if (idx < bidx) {
                            bi = inter; bS = S; bidx = idx; bk = b2 + s;
                        }
                    }
                }
            }
        }
    }

    // butterfly combine across the LPR lanes of this roi (deterministic)
    #pragma unroll
    for (int off = 1; off < LPR; off <<= 1) {
        float obi  = __shfl_xor_sync(0xffffffffu, bi, off);
        float obS  = __shfl_xor_sync(0xffffffffu, bS, off);
        int   oidx = __shfl_xor_sync(0xffffffffu, bidx, off);
        int   obk  = __shfl_xor_sync(0xffffffffu, bk, off);
        float p1 = obi * bS;
        float p2 = bi * obS;
        if (p1 > p2 || (p1 == p2 && oidx < bidx)) {
            bi = obi; bS = obS; bidx = oidx; bk = obk;
        }
    }

    float maxiou = bi / (bS - bi);
    float maskf  = (maxiou > 0.5f) ? 1.0f : 0.0f;

    // n_matched: count par==0 lanes only
    unsigned bal = __ballot_sync(0xffffffffu, (par == 0) && maskf > 0.0f);
    if (lane == 0) s_wcnt[warp] = __popc(bal);
    __syncthreads();
    if (t == 0) {
        int tot = 0;
        #pragma unroll
        for (int w = 0; w < 8; ++w) tot += s_wcnt[w];
        if (tot) atomicAdd(&g_nmatch, tot);
    }

    if (par != 0) return;                  // epilogue by lead lane only

    // inverse_transform (with +1 on w/h, matching reference)
    float w0 = rx2 - rx1 + 1.0f, h0 = ry2 - ry1 + 1.0f;
    float cxx = rx1 + 0.5f * w0, cyy = ry1 + 0.5f * h0;
    float pcx = d.x * w0 + cxx,  pcy = d.y * h0 + cyy;
    float pw = expf(d.z) * w0,   ph = expf(d.w) * h0;
    float f1 = pcx - 0.5f * pw, f2 = pcy - 0.5f * ph;
    float f3 = pcx + 0.5f * pw, f4 = pcy + 0.5f * ph;

    float loss = 0.0f;
    if (maskf > 0.0f) {
        float4 A = __ldg(&g_binA[bk]);
        float gx2 = A.x, gy2 = A.y, gx1 = -A.z, gy1 = -A.w;
        float iw = fmaxf(fminf(f3, gx2) - fmaxf(f1, gx1), 0.0f);
        float ih = fmaxf(fminf(f4, gy2) - fmaxf(f2, gy1), 0.0f);
        float it = iw * ih;
        float aa = (f3 - f1) * (f4 - f2);
        float ab = (gx2 - gx1) * (gy2 - gy1);
        float io = it / (aa + ab - it);
        loss = -logf(io + 0.1f);
    }

    out[i] = loss;
    float2* outr = reinterpret_cast<float2*>(out + N_ROIS + 2);
    outr[2 * i + 0] = make_float2(f1 * maskf, f2 * maskf);
    outr[2 * i + 1] = make_float2(f3 * maskf, f4 * maskf);
    g_maskf[i] = maskf;
}

// == feat: INTERLEAVED rows (balance masked rows across all 128 blocks) ==
__global__ void __launch_bounds__(256) kfeat(const float* __restrict__ feat,
                                             float* __restrict__ out) {
    __shared__ int   s_rows[256];
    __shared__ int   s_wcnt[8];
    __shared__ int   s_isLast;
    __shared__ float s_red[256];
    int t = threadIdx.x;
    int lane = t & 31, warp = t >> 5;
    int blk = blockIdx.x;

    float m = g_maskf[blk + NFEAT_BLK * t];      // strided row j = t
    unsigned bal = __ballot_sync(0xffffffffu, m != 0.0f);
    if (lane == 0) s_wcnt[warp] = __popc(bal);
    __syncthreads();
    int base = 0, total = 0;
    #pragma unroll
    for (int w = 0; w < 8; ++w) {
        int cw = s_wcnt[w];
        if (w < warp) base += cw;
        total += cw;
    }
    if (m != 0.0f)
        s_rows[base + __popc(bal & ((1u << lane) - 1u))] = t;  // store j
    __syncthreads();

    float a0 = 0.0f, a1 = 0.0f;
    int j = 0;
    for (; j + 4 <= total; j += 4) {          // unroll x4 for load MLP
        size_t r0 = (size_t)(blk + NFEAT_BLK * s_rows[j])     * D_FEAT;
        size_t r1 = (size_t)(blk + NFEAT_BLK * s_rows[j + 1]) * D_FEAT;
        size_t r2 = (size_t)(blk + NFEAT_BLK * s_rows[j + 2]) * D_FEAT;
        size_t r3 = (size_t)(blk + NFEAT_BLK * s_rows[j + 3]) * D_FEAT;
        float v0 = feat[r0 + t];
        float v1 = feat[r0 + t + 256];
        float v2 = feat[r1 + t];
        float v3 = feat[r1 + t + 256];
        float v4 = feat[r2 + t];
        float v5 = feat[r2 + t + 256];
        float v6 = feat[r3 + t];
        float v7 = feat[r3 + t + 256];
        a0 += (v0 + v2) + (v4 + v6);
        a1 += (v1 + v3) + (v5 + v7);
    }
    for (; j < total; ++j) {
        size_t r0 = (size_t)(blk + NFEAT_BLK * s_rows[j]) * D_FEAT;
        a0 += feat[r0 + t];
        a1 += feat[r0 + t + 256];
    }
    g_partial[blk * D_FEAT + t]       = a0;
    g_partial[blk * D_FEAT + t + 256] = a1;

    __threadfence();
    if (t == 0) s_isLast = (atomicAdd(&g_done, 1) == NFEAT_BLK - 1);
    __syncthreads();
    if (!s_isLast) return;

    float c0 = 0.0f, c1 = 0.0f;
    #pragma unroll 8
    for (int b = 0; b < NFEAT_BLK; ++b) {
        c0 += g_partial[b * D_FEAT + t];
        c1 += g_partial[b * D_FEAT + t + 256];
    }
    s_red[t] = fabsf(c0) + fabsf(c1);
    __syncthreads();
    #pragma unroll
    for (int off = 128; off > 0; off >>= 1) {
        if (t < off) s_red[t] += s_red[t + off];
        __syncthreads();
    }
    if (t == 0) {
        out[N_ROIS]         = (float)g_nmatch;   // n_matched
        out[N_ROIS + 1]     = (float)N_ROIS;     // num_rois
        out[5 * N_ROIS + 2] = s_red[0];          // feat_loss
    }
    // reset bin counters for the NEXT graph replay (consumed by then)
    #pragma unroll
    for (int j2 = 0; j2 < NCELL / 256; ++j2)
        g_cnt[t + j2 * 256] = 0;
}

// ---------------- launch ----------------
extern "C" void kernel_launch(void* const* d_in, const int* in_sizes, int n_in,
                              void* d_out, int out_size) {
    const float* rois = (const float*)d_in[0];
    const float* pred = (const float*)d_in[1];
    const float* gt   = (const float*)d_in[2];
    const float* feat = (const float*)d_in[3];
    float* out = (float*)d_out;

    kbin<<<(M_GT + 255) / 256, 256>>>(gt);
    kmatch<<<N_ROIS / (256 / LPR), 256>>>(rois, pred, out);
    kfeat<<<NFEAT_BLK, 256>>>(feat, out);
}